// round 10
// baseline (speedup 1.0000x reference)
#include <cuda_runtime.h>
#include <cuda_fp16.h>
#include <cstdint>

#define M_Q   4096
#define N_B   65536
#define D_DIM 128
#define KNN   9
#define MTILE 128
#define NTILE 128
#define NSPLIT 9                      // one-wave grid: 32*9 = 288 CTAs, 2/SM
#define NT_TOTAL (N_B / NTILE)        // 512 n-tiles
#define THREADS 384                   // 8 tensor warps + 4 SIMT warps
#define PART_STRIDE 12
#define NLISTS (NSPLIT * 2)
#define TILE_HALFS (128 * D_DIM)
#define TCOLS 80                      // tensor columns (10 n8-blocks)
#define SCOLS_H 24                    // simt cols per lane-half (3 passes of 8)

// ---------------------------------------------------------------------------
// Device-global scratch
// ---------------------------------------------------------------------------
__device__ __align__(16) float g_bsq[N_B];
__device__ __align__(16) float g_qsq[M_Q];
__device__ __align__(16) float g_part[NLISTS * M_Q * PART_STRIDE];
__device__ __align__(16) __half g_bt[(size_t)N_B * D_DIM];   // packed pre-swizzled
__device__ __align__(16) __half g_qt[(size_t)M_Q * D_DIM];

// ---------------------------------------------------------------------------
// SMEM: A 32KB, B 2x32KB, bsq 2x512B, mbarriers
// ---------------------------------------------------------------------------
#define OFF_A    0
#define OFF_B    32768
#define OFF_BSQ  (32768 + 2 * 32768)        // 98304
#define OFF_MBAR (OFF_BSQ + 2 * 512)        // 99328
#define SMEM_SZ  (OFF_MBAR + 64)

// ---------------------------------------------------------------------------
// PTX helpers (sm_90-baseline)
// ---------------------------------------------------------------------------
__device__ __forceinline__ uint32_t smem_u32(const void* p) {
    uint32_t a;
    asm("{ .reg .u64 t; cvta.to.shared.u64 t, %1; cvt.u32.u64 %0, t; }" : "=r"(a) : "l"(p));
    return a;
}
__device__ __forceinline__ void ldsm4(uint32_t* r, uint32_t addr) {
    asm volatile("ldmatrix.sync.aligned.m8n8.x4.shared.b16 {%0,%1,%2,%3}, [%4];"
                 : "=r"(r[0]), "=r"(r[1]), "=r"(r[2]), "=r"(r[3]) : "r"(addr));
}
__device__ __forceinline__ void mma16816_f16(uint32_t* c, const uint32_t* a, const uint32_t* b) {
    asm volatile(
        "mma.sync.aligned.m16n8k16.row.col.f16.f16.f16.f16 "
        "{%0,%1}, {%2,%3,%4,%5}, {%6,%7}, {%0,%1};"
        : "+r"(c[0]), "+r"(c[1])
        : "r"(a[0]), "r"(a[1]), "r"(a[2]), "r"(a[3]), "r"(b[0]), "r"(b[1]));
}
#define MBAR_INIT(a, c) \
    asm volatile("mbarrier.init.shared.b64 [%0], %1;" :: "r"(a), "r"(c) : "memory")
#define MBAR_EXPECT_TX(a, tx) \
    asm volatile("mbarrier.arrive.expect_tx.shared.b64 _, [%0], %1;" :: "r"(a), "r"(tx) : "memory")
#define MBAR_WAIT(a, ph) do {                                                   \
    asm volatile(                                                               \
        "{\n\t.reg .pred P1;\n\t"                                               \
        "WAIT_LOOP_%=:\n\t"                                                     \
        "mbarrier.try_wait.parity.acquire.cta.shared::cta.b64 P1, [%0], %1, 0x989680;\n\t" \
        "@P1 bra.uni WAIT_DONE_%=;\n\t"                                         \
        "bra.uni WAIT_LOOP_%=;\n\t"                                             \
        "WAIT_DONE_%=:\n\t}"                                                    \
        :: "r"(a), "r"(ph) : "memory");                                         \
} while (0)
__device__ __forceinline__ void bulk_g2s(uint32_t dst, const void* src,
                                         uint32_t bytes, uint32_t mbar) {
    asm volatile(
        "cp.async.bulk.shared::cluster.global.mbarrier::complete_tx::bytes "
        "[%0], [%1], %2, [%3];"
        :: "r"(dst), "l"(src), "r"(bytes), "r"(mbar) : "memory");
}

// ---------------------------------------------------------------------------
// Pre-pass: fp32 -> fp16 packed pre-swizzled tiles + fused squared norms
// ---------------------------------------------------------------------------
__global__ void pack_norms_kernel(const float4* __restrict__ src,
                                  uint4* __restrict__ dst,
                                  float* __restrict__ nrm, int nchunks) {
    int i = blockIdx.x * blockDim.x + threadIdx.x;
    if (i >= nchunks) return;
    int vec = i >> 4, c = i & 15;
    int tile = vec >> 7, r = vec & 127;
    float4 a = src[2 * i];
    float4 b = src[2 * i + 1];
    __half2 h0 = __floats2half2_rn(a.x, a.y);
    __half2 h1 = __floats2half2_rn(a.z, a.w);
    __half2 h2 = __floats2half2_rn(b.x, b.y);
    __half2 h3 = __floats2half2_rn(b.z, b.w);
    uint4 o;
    o.x = *(uint32_t*)&h0; o.y = *(uint32_t*)&h1;
    o.z = *(uint32_t*)&h2; o.w = *(uint32_t*)&h3;
    uint32_t off = (uint32_t)tile * 32768 + r * 256 + (((uint32_t)(c ^ (r & 7))) << 4);
    dst[off >> 4] = o;

    float s = a.x * a.x + a.y * a.y + a.z * a.z + a.w * a.w
            + b.x * b.x + b.y * b.y + b.z * b.z + b.w * b.w;
#pragma unroll
    for (int offv = 8; offv; offv >>= 1) s += __shfl_xor_sync(0xffffffffu, s, offv);
    if (c == 0) nrm[vec] = s;
}

// ---------------------------------------------------------------------------
// Streaming top-9
// ---------------------------------------------------------------------------
__device__ __forceinline__ void top9f(float s, float (&h)[KNN], float& thr) {
    if (s < thr) {
        bool done = false;
#pragma unroll
        for (int i = 0; i < KNN; i++)
            if (!done && h[i] == thr) { h[i] = s; done = true; }
        float m = h[0];
#pragma unroll
        for (int i = 1; i < KNN; i++) m = fmaxf(m, h[i]);
        thr = m;
    }
}

// ---------------------------------------------------------------------------
// Main kernel: hybrid tensor(cols 0-79) + SIMT HFMA2-chunked(cols 80-127)
// grid = (32, 9), 384 threads, 2 CTAs/SM
// ---------------------------------------------------------------------------
__global__ void __launch_bounds__(THREADS, 2) knn_main_kernel() {
    extern __shared__ char smem[];
    const uint32_t sm = smem_u32(smem);
    const int tid  = threadIdx.x;
    const int wid  = tid >> 5;
    const int lane = tid & 31;
    const int qtile = blockIdx.x;
    const int qbase = qtile * MTILE;
    const int b0  = (NT_TOTAL * blockIdx.y) / NSPLIT;
    const int cnt = (NT_TOTAL * (blockIdx.y + 1)) / NSPLIT - b0;
    const float INF = __int_as_float(0x7f800000);
    const unsigned FULL = 0xffffffffu;

    if (tid == 0) { MBAR_INIT(sm + OFF_MBAR, 1); MBAR_INIT(sm + OFF_MBAR + 8, 1); }
    __syncthreads();

    if (tid == 0) {
        MBAR_EXPECT_TX(sm + OFF_MBAR, 32768u + 32768u + 512u);
        bulk_g2s(sm + OFF_A, g_qt + (size_t)qtile * TILE_HALFS, 32768u, sm + OFF_MBAR);
        bulk_g2s(sm + OFF_B, g_bt + (size_t)b0 * TILE_HALFS, 32768u, sm + OFF_MBAR);
        bulk_g2s(sm + OFF_BSQ, g_bsq + b0 * NTILE, 512u, sm + OFF_MBAR);
        MBAR_EXPECT_TX(sm + OFF_MBAR + 8, 32768u + 512u);
        bulk_g2s(sm + OFF_B + 32768, g_bt + (size_t)(b0 + 1) * TILE_HALFS, 32768u,
                 sm + OFF_MBAR + 8);
        bulk_g2s(sm + OFF_BSQ + 512, g_bsq + (b0 + 1) * NTILE, 512u, sm + OFF_MBAR + 8);
    }

    MBAR_WAIT(sm + OFF_MBAR, 0);

    float heap0[KNN], heap1[KNN];
    float thr0 = INF, thr1 = INF;
#pragma unroll
    for (int i = 0; i < KNN; i++) { heap0[i] = INF; heap1[i] = INF; }

    // tensor lane invariants
    const int g    = lane >> 2;
    const int tig  = lane & 3;
    const int rA   = lane & 15;
    const int shiA = lane >> 4;
    const int rB   = (lane & 7) + ((lane >> 4) << 3);
    const int shiB = (lane >> 3) & 1;
    const uint32_t arow = sm + OFF_A + (wid * 16 + rA) * 256;

    // simt lane invariants
    const int sid = (wid - 8) * 32 + lane;   // 0..127 on simt warps
    const int r0  = 2 * (sid >> 1);
    const int r1  = r0 + 1;
    const int hh  = sid & 1;
    const int rs0 = r0 & 7, rs1 = r1 & 7;

#pragma unroll 1
    for (int t = 0; t < cnt; t++) {
        const int buf = t & 1;
        if (t > 0) MBAR_WAIT(sm + OFF_MBAR + buf * 8, (t >> 1) & 1);

        const uint32_t Bb = sm + OFF_B + buf * 32768;
        const float* bsq = (const float*)(smem + OFF_BSQ + buf * 512);

        if (wid < 8) {
            // ============ tensor path: cols 0..79 (10 n8-blocks) ============
            uint32_t acc[10][2];
#pragma unroll
            for (int j = 0; j < 10; j++) { acc[j][0] = 0u; acc[j][1] = 0u; }

#pragma unroll
            for (int pass = 0; pass < 2; pass++) {
                uint32_t aF[4][4];
#pragma unroll
                for (int ss = 0; ss < 4; ss++)
                    ldsm4(aF[ss], arow +
                          ((((uint32_t)(2 * (pass * 4 + ss) + shiA)) ^ (uint32_t)(rA & 7)) << 4));
#pragma unroll
                for (int ss = 0; ss < 4; ss++) {
                    const uint32_t segoff =
                        (((uint32_t)(2 * (pass * 4 + ss) + shiB)) ^ (uint32_t)(rB & 7)) << 4;
#pragma unroll
                    for (int p = 0; p < 5; p++) {
                        uint32_t bf[4];
                        ldsm4(bf, Bb + (p * 16 + rB) * 256 + segoff);
                        mma16816_f16(acc[2 * p],     aF[ss], bf);
                        mma16816_f16(acc[2 * p + 1], aF[ss], bf + 2);
                    }
                }
            }
#pragma unroll
            for (int j = 0; j < 10; j++) {
                const int col = j * 8 + 2 * tig;
                float bx = bsq[col], by = bsq[col + 1];
                float2 v0 = __half22float2(*(const __half2*)&acc[j][0]);
                float2 v1 = __half22float2(*(const __half2*)&acc[j][1]);
                top9f(fmaf(-2.0f, v0.x, bx), heap0, thr0);
                top9f(fmaf(-2.0f, v0.y, by), heap0, thr0);
                top9f(fmaf(-2.0f, v1.x, bx), heap1, thr1);
                top9f(fmaf(-2.0f, v1.y, by), heap1, thr1);
            }
        } else {
            // ===== SIMT path: cols 80..127, chunked HFMA2 -> fp32 =====
            const char* As = smem + OFF_A;
            const char* Bs = smem + OFF_B + buf * 32768;
            const uint32_t aoff0 = r0 * 256;
            const uint32_t aoff1 = r1 * 256;

#pragma unroll 1
            for (int pass = 0; pass < 3; pass++) {
                const int colbase = TCOLS + hh * SCOLS_H + pass * 8;
                float acc0[8], acc1[8];
#pragma unroll
                for (int n = 0; n < 8; n++) { acc0[n] = 0.0f; acc1[n] = 0.0f; }

#pragma unroll
                for (int c = 0; c < 8; c++) {   // 16 k-elements per chunk
                    uint4 a0a = *(const uint4*)(As + aoff0 + (((uint32_t)((2 * c)     ^ rs0)) << 4));
                    uint4 a0b = *(const uint4*)(As + aoff0 + (((uint32_t)((2 * c + 1) ^ rs0)) << 4));
                    uint4 a1a = *(const uint4*)(As + aoff1 + (((uint32_t)((2 * c)     ^ rs1)) << 4));
                    uint4 a1b = *(const uint4*)(As + aoff1 + (((uint32_t)((2 * c + 1) ^ rs1)) << 4));
                    __half2 a0[8], a1[8];
                    a0[0] = *(__half2*)&a0a.x; a0[1] = *(__half2*)&a0a.y;
                    a0[2] = *(__half2*)&a0a.z; a0[3] = *(__half2*)&a0a.w;
                    a0[4] = *(__half2*)&a0b.x; a0[5] = *(__half2*)&a0b.y;
                    a0[6] = *(__half2*)&a0b.z; a0[7] = *(__half2*)&a0b.w;
                    a1[0] = *(__half2*)&a1a.x; a1[1] = *(__half2*)&a1a.y;
                    a1[2] = *(__half2*)&a1a.z; a1[3] = *(__half2*)&a1a.w;
                    a1[4] = *(__half2*)&a1b.x; a1[5] = *(__half2*)&a1b.y;
                    a1[6] = *(__half2*)&a1b.z; a1[7] = *(__half2*)&a1b.w;

#pragma unroll
                    for (int n = 0; n < 8; n++) {
                        const int col = colbase + n;
                        const char* bp = Bs + col * 256;
                        uint4 bA = *(const uint4*)(bp + (((uint32_t)((2 * c)     ^ (col & 7))) << 4));
                        uint4 bB = *(const uint4*)(bp + (((uint32_t)((2 * c + 1) ^ (col & 7))) << 4));
                        __half2 bb[8];
                        bb[0] = *(__half2*)&bA.x; bb[1] = *(__half2*)&bA.y;
                        bb[2] = *(__half2*)&bA.z; bb[3] = *(__half2*)&bA.w;
                        bb[4] = *(__half2*)&bB.x; bb[5] = *(__half2*)&bB.y;
                        bb[6] = *(__half2*)&bB.z; bb[7] = *(__half2*)&bB.w;

                        __half2 s0 = __half2half2(__ushort_as_half(0));
                        __half2 s1 = s0;
#pragma unroll
                        for (int e = 0; e < 8; e++) {
                            s0 = __hfma2(a0[e], bb[e], s0);
                            s1 = __hfma2(a1[e], bb[e], s1);
                        }
                        float2 f0 = __half22float2(s0);
                        float2 f1 = __half22float2(s1);
                        acc0[n] += f0.x; acc0[n] += f0.y;
                        acc1[n] += f1.x; acc1[n] += f1.y;
                    }
                }

#pragma unroll
                for (int n = 0; n < 8; n++) {
                    const int col = colbase + n;
                    float bq = bsq[col];
                    top9f(fmaf(-2.0f, acc0[n], bq), heap0, thr0);
                    top9f(fmaf(-2.0f, acc1[n], bq), heap1, thr1);
                }
            }
        }

        __syncthreads();
        if (t + 2 < cnt && tid == 0) {
            MBAR_EXPECT_TX(sm + OFF_MBAR + buf * 8, 32768u + 512u);
            bulk_g2s(sm + OFF_B + buf * 32768,
                     g_bt + (size_t)(b0 + t + 2) * TILE_HALFS, 32768u,
                     sm + OFF_MBAR + buf * 8);
            bulk_g2s(sm + OFF_BSQ + buf * 512, g_bsq + (b0 + t + 2) * NTILE, 512u,
                     sm + OFF_MBAR + buf * 8);
        }
    }

    // ---------------- merges + list writes ----------------
    if (wid < 8) {
        // quad merge (safe: source lanes never mutate, only tig==0 inserts)
#pragma unroll
        for (int src = 1; src < 4; src++) {
#pragma unroll
            for (int i = 0; i < KNN; i++) {
                float v0 = __shfl_sync(FULL, heap0[i], (lane & ~3) + src);
                float v1 = __shfl_sync(FULL, heap1[i], (lane & ~3) + src);
                if (tig == 0) { top9f(v0, heap0, thr0); top9f(v1, heap1, thr1); }
            }
        }
        if (tig == 0) {
            const int row0 = qbase + wid * 16 + g;
            size_t p0 = ((size_t)(blockIdx.y * 2) * M_Q + row0) * PART_STRIDE;
            size_t p1 = ((size_t)(blockIdx.y * 2) * M_Q + row0 + 8) * PART_STRIDE;
#pragma unroll
            for (int r = 0; r < KNN; r++) { g_part[p0 + r] = heap0[r]; g_part[p1 + r] = heap1[r]; }
        }
    } else {
        // pair merge — TWO-PHASE: snapshot partner's lists BEFORE any insert
        // (R8/R9 read the partner's heap while it was being mutated -> lost
        //  true top-9 entries -> the 2.5e-3 failures)
        float t0[KNN], t1[KNN];
#pragma unroll
        for (int i = 0; i < KNN; i++) {
            t0[i] = __shfl_xor_sync(FULL, heap0[i], 1);
            t1[i] = __shfl_xor_sync(FULL, heap1[i], 1);
        }
#pragma unroll
        for (int i = 0; i < KNN; i++) {
            top9f(t0[i], heap0, thr0);
            top9f(t1[i], heap1, thr1);
        }
        if (hh == 0) {
            size_t p0 = ((size_t)(blockIdx.y * 2 + 1) * M_Q + qbase + r0) * PART_STRIDE;
            size_t p1 = ((size_t)(blockIdx.y * 2 + 1) * M_Q + qbase + r1) * PART_STRIDE;
#pragma unroll
            for (int r = 0; r < KNN; r++) { g_part[p0 + r] = heap0[r]; g_part[p1 + r] = heap1[r]; }
        }
    }
}

// ---------------------------------------------------------------------------
// Finalize: stream 18 lists x 9 = 162 candidates through a register heap
// ---------------------------------------------------------------------------
__global__ void knn_finalize_kernel(float* __restrict__ out) {
    int qi = blockIdx.x * blockDim.x + threadIdx.x;
    if (qi >= M_Q) return;
    const float INF = __int_as_float(0x7f800000);
    float heap[KNN], thr = INF;
#pragma unroll
    for (int i = 0; i < KNN; i++) heap[i] = INF;

#pragma unroll 1
    for (int l = 0; l < NLISTS; l++) {
        const float* p = &g_part[((size_t)l * M_Q + qi) * PART_STRIDE];
#pragma unroll
        for (int r = 0; r < KNN; r++) top9f(p[r], heap, thr);
    }

    float qsq = g_qsq[qi];
    float sum = 0.0f;
#pragma unroll
    for (int i = 0; i < KNN; i++) sum += sqrtf(fmaxf(heap[i] + qsq, 0.0f));
    out[qi] = sum * (1.0f / KNN);
}

// ---------------------------------------------------------------------------
extern "C" void kernel_launch(void* const* d_in, const int* in_sizes, int n_in,
                              void* d_out, int out_size)
{
    const float* q = (const float*)d_in[0];   // features    [4096,128]
    const float* b = (const float*)d_in[1];   // memory_bank [65536,128]
    if (n_in >= 2 && in_sizes[0] > in_sizes[1]) {
        const float* tmp = q; q = b; b = tmp;
    }
    float* out = (float*)d_out;

    static uint4* p_bt = nullptr;
    static uint4* p_qt = nullptr;
    static float *p_bsq = nullptr, *p_qsq = nullptr;
    if (!p_bt) {
        cudaGetSymbolAddress((void**)&p_bt, g_bt);
        cudaGetSymbolAddress((void**)&p_qt, g_qt);
        cudaGetSymbolAddress((void**)&p_bsq, g_bsq);
        cudaGetSymbolAddress((void**)&p_qsq, g_qsq);
    }

    cudaFuncSetAttribute(knn_main_kernel,
                         cudaFuncAttributeMaxDynamicSharedMemorySize, SMEM_SZ);

    pack_norms_kernel<<<N_B * 16 / 256, 256>>>((const float4*)b, p_bt, p_bsq, N_B * 16);
    pack_norms_kernel<<<M_Q * 16 / 256, 256>>>((const float4*)q, p_qt, p_qsq, M_Q * 16);

    dim3 grid(M_Q / MTILE, NSPLIT);
    knn_main_kernel<<<grid, THREADS, SMEM_SZ>>>();

    knn_finalize_kernel<<<M_Q / 256, 256>>>(out);
}

// round 12
// speedup vs baseline: 2.2883x; 2.2883x over previous
#include <cuda_runtime.h>
#include <cuda_fp16.h>
#include <cstdint>

#define M_Q   4096
#define N_B   65536
#define D_DIM 128
#define KNN   9
#define MTILE 128
#define NTILE 128
#define NCTAS 296                     // exactly 2 per SM on 148 SMs
#define THREADS 256
#define NSLOTS 12                     // max covering CTAs per qtile is 11
#define TILE_HALFS (128 * D_DIM)      // 16384 halves = 32KB per packed tile

// ---------------------------------------------------------------------------
// Device-global scratch
// ---------------------------------------------------------------------------
__device__ __align__(16) float g_bsq[N_B];
__device__ __align__(16) float g_qsq[M_Q];
// query-major candidate lists: [query][slot][KNN..pad12]
__device__ __align__(16) float g_part[(size_t)M_Q * NSLOTS * 12];
__device__ __align__(16) __half g_bt[(size_t)N_B * D_DIM];   // packed pre-swizzled
__device__ __align__(16) __half g_qt[(size_t)M_Q * D_DIM];

// ---------------------------------------------------------------------------
// SMEM: A 32KB, B 2x32KB, bsq 2x512B, mbarriers (buf0, buf1, A)
// ---------------------------------------------------------------------------
#define OFF_A    0
#define OFF_B    32768
#define OFF_BSQ  (32768 + 2 * 32768)        // 98304
#define OFF_MBAR (OFF_BSQ + 2 * 512)        // 99328
#define SMEM_SZ  (OFF_MBAR + 64)

// ---------------------------------------------------------------------------
// PTX helpers (sm_90-baseline)
// ---------------------------------------------------------------------------
__device__ __forceinline__ uint32_t smem_u32(const void* p) {
    uint32_t a;
    asm("{ .reg .u64 t; cvta.to.shared.u64 t, %1; cvt.u32.u64 %0, t; }" : "=r"(a) : "l"(p));
    return a;
}
__device__ __forceinline__ void ldsm4(uint32_t* r, uint32_t addr) {
    asm volatile("ldmatrix.sync.aligned.m8n8.x4.shared.b16 {%0,%1,%2,%3}, [%4];"
                 : "=r"(r[0]), "=r"(r[1]), "=r"(r[2]), "=r"(r[3]) : "r"(addr));
}
__device__ __forceinline__ void mma16816_f16(uint32_t* c, const uint32_t* a, const uint32_t* b) {
    asm volatile(
        "mma.sync.aligned.m16n8k16.row.col.f16.f16.f16.f16 "
        "{%0,%1}, {%2,%3,%4,%5}, {%6,%7}, {%0,%1};"
        : "+r"(c[0]), "+r"(c[1])
        : "r"(a[0]), "r"(a[1]), "r"(a[2]), "r"(a[3]), "r"(b[0]), "r"(b[1]));
}
#define MBAR_INIT(a, c) \
    asm volatile("mbarrier.init.shared.b64 [%0], %1;" :: "r"(a), "r"(c) : "memory")
#define MBAR_EXPECT_TX(a, tx) \
    asm volatile("mbarrier.arrive.expect_tx.shared.b64 _, [%0], %1;" :: "r"(a), "r"(tx) : "memory")
#define MBAR_WAIT(a, ph) do {                                                   \
    asm volatile(                                                               \
        "{\n\t.reg .pred P1;\n\t"                                               \
        "WAIT_LOOP_%=:\n\t"                                                     \
        "mbarrier.try_wait.parity.acquire.cta.shared::cta.b64 P1, [%0], %1, 0x989680;\n\t" \
        "@P1 bra.uni WAIT_DONE_%=;\n\t"                                         \
        "bra.uni WAIT_LOOP_%=;\n\t"                                             \
        "WAIT_DONE_%=:\n\t}"                                                    \
        :: "r"(a), "r"(ph) : "memory");                                         \
} while (0)
__device__ __forceinline__ void bulk_g2s(uint32_t dst, const void* src,
                                         uint32_t bytes, uint32_t mbar) {
    asm volatile(
        "cp.async.bulk.shared::cluster.global.mbarrier::complete_tx::bytes "
        "[%0], [%1], %2, [%3];"
        :: "r"(dst), "l"(src), "r"(bytes), "r"(mbar) : "memory");
}

// ---------------------------------------------------------------------------
// Pre-pass: fp32 -> fp16 packed pre-swizzled tiles + fused squared norms
// ---------------------------------------------------------------------------
__global__ void pack_norms_kernel(const float4* __restrict__ src,
                                  uint4* __restrict__ dst,
                                  float* __restrict__ nrm, int nchunks) {
    int i = blockIdx.x * blockDim.x + threadIdx.x;
    if (i >= nchunks) return;
    int vec = i >> 4, c = i & 15;
    int tile = vec >> 7, r = vec & 127;
    float4 a = src[2 * i];
    float4 b = src[2 * i + 1];
    __half2 h0 = __floats2half2_rn(a.x, a.y);
    __half2 h1 = __floats2half2_rn(a.z, a.w);
    __half2 h2 = __floats2half2_rn(b.x, b.y);
    __half2 h3 = __floats2half2_rn(b.z, b.w);
    uint4 o;
    o.x = *(uint32_t*)&h0; o.y = *(uint32_t*)&h1;
    o.z = *(uint32_t*)&h2; o.w = *(uint32_t*)&h3;
    uint32_t off = (uint32_t)tile * 32768 + r * 256 + (((uint32_t)(c ^ (r & 7))) << 4);
    dst[off >> 4] = o;

    float s = a.x * a.x + a.y * a.y + a.z * a.z + a.w * a.w
            + b.x * b.x + b.y * b.y + b.z * b.z + b.w * b.w;
#pragma unroll
    for (int offv = 8; offv; offv >>= 1) s += __shfl_xor_sync(0xffffffffu, s, offv);
    if (c == 0) nrm[vec] = s;
}

// ---------------------------------------------------------------------------
// Streaming top-9
// ---------------------------------------------------------------------------
__device__ __forceinline__ void top9f(float s, float (&h)[KNN], float& thr) {
    if (s < thr) {
        bool done = false;
#pragma unroll
        for (int i = 0; i < KNN; i++)
            if (!done && h[i] == thr) { h[i] = s; done = true; }
        float m = h[0];
#pragma unroll
        for (int i = 1; i < KNN; i++) m = fmaxf(m, h[i]);
        thr = m;
    }
}

// ---------------------------------------------------------------------------
// Main kernel: flattened job decomposition, fp16-acc mma.sync + top-9.
// Grid = 296 CTAs; CTA c handles jobs [2048c/37, 2048(c+1)/37) where
// job j = (qtile = j>>9, ntile = j&511). At most 2 qtile segments per CTA.
// ---------------------------------------------------------------------------
__global__ void __launch_bounds__(THREADS, 2) knn_main_kernel() {
    extern __shared__ char smem[];
    const uint32_t sm = smem_u32(smem);
    const int tid  = threadIdx.x;
    const int wid  = tid >> 5;
    const int lane = tid & 31;
    const int g    = lane >> 2;
    const int tig  = lane & 3;
    const int c    = blockIdx.x;
    const int j0   = (c * 2048) / 37;
    const int j1   = ((c + 1) * 2048) / 37;
    const int cnt  = j1 - j0;                 // 55 or 56
    const int lastQ = (j1 - 1) >> 9;
    const float INF = __int_as_float(0x7f800000);
    const unsigned FULL = 0xffffffffu;

    int curQ = j0 >> 9;

    if (tid == 0) {
        MBAR_INIT(sm + OFF_MBAR, 1);
        MBAR_INIT(sm + OFF_MBAR + 8, 1);
        MBAR_INIT(sm + OFF_MBAR + 16, 1);     // A barrier
    }
    __syncthreads();

    // ---- prologue: A(curQ), B(j0), B(j0+1)
    if (tid == 0) {
        MBAR_EXPECT_TX(sm + OFF_MBAR + 16, 32768u);
        bulk_g2s(sm + OFF_A, g_qt + (size_t)curQ * TILE_HALFS, 32768u, sm + OFF_MBAR + 16);
        MBAR_EXPECT_TX(sm + OFF_MBAR, 32768u + 512u);
        bulk_g2s(sm + OFF_B, g_bt + (size_t)(j0 & 511) * TILE_HALFS, 32768u, sm + OFF_MBAR);
        bulk_g2s(sm + OFF_BSQ, g_bsq + (j0 & 511) * NTILE, 512u, sm + OFF_MBAR);
        MBAR_EXPECT_TX(sm + OFF_MBAR + 8, 32768u + 512u);
        bulk_g2s(sm + OFF_B + 32768, g_bt + (size_t)((j0 + 1) & 511) * TILE_HALFS, 32768u,
                 sm + OFF_MBAR + 8);
        bulk_g2s(sm + OFF_BSQ + 512, g_bsq + ((j0 + 1) & 511) * NTILE, 512u, sm + OFF_MBAR + 8);
    }

    // lane invariants for ldmatrix addressing
    const int rA   = lane & 15;
    const int shiA = lane >> 4;
    const int rB   = (lane & 7) + ((lane >> 4) << 3);
    const int shiB = (lane >> 3) & 1;
    const uint32_t arow = sm + OFF_A + (wid * 16 + rA) * 256;

    // ---- wait A, preload A fragments
    MBAR_WAIT(sm + OFF_MBAR + 16, 0);
    uint32_t aF[8][4];
#pragma unroll
    for (int s = 0; s < 8; s++)
        ldsm4(aF[s], arow + ((((uint32_t)(2 * s + shiA)) ^ (uint32_t)(rA & 7)) << 4));
    __syncthreads();   // all warps done reading A smem

    // prefetch second segment's A tile (overwrites A smem; aF already in regs)
    if (lastQ != curQ && tid == 0) {
        MBAR_EXPECT_TX(sm + OFF_MBAR + 16, 32768u);
        bulk_g2s(sm + OFF_A, g_qt + (size_t)lastQ * TILE_HALFS, 32768u, sm + OFF_MBAR + 16);
    }

    float heap0[KNN], heap1[KNN];
    float thr0 = INF, thr1 = INF;
#pragma unroll
    for (int i = 0; i < KNN; i++) { heap0[i] = INF; heap1[i] = INF; }

#pragma unroll 1
    for (int t = 0; t < cnt; t++) {
        const int j = j0 + t;
        const int buf = t & 1;

        // R11 BUG FIX: wait unconditionally (t=0 raced ahead of B0's TMA)
        MBAR_WAIT(sm + OFF_MBAR + buf * 8, (t >> 1) & 1);

        // ---- qtile boundary: flush heaps for curQ, load new A fragments
        if ((j >> 9) != curQ) {
            // quad merge tig 1..3 -> tig 0 (source lanes never mutate: safe)
#pragma unroll
            for (int src = 1; src < 4; src++) {
#pragma unroll
                for (int i = 0; i < KNN; i++) {
                    float v0 = __shfl_sync(FULL, heap0[i], (lane & ~3) + src);
                    float v1 = __shfl_sync(FULL, heap1[i], (lane & ~3) + src);
                    if (tig == 0) { top9f(v0, heap0, thr0); top9f(v1, heap1, thr1); }
                }
            }
            if (tig == 0) {
                const int slot = c - ((37 * curQ) >> 2);
                const int row0 = (curQ << 7) + wid * 16 + g;
                size_t p0 = ((size_t)row0 * NSLOTS + slot) * 12;
                size_t p1 = ((size_t)(row0 + 8) * NSLOTS + slot) * 12;
#pragma unroll
                for (int r = 0; r < KNN; r++) { g_part[p0 + r] = heap0[r]; g_part[p1 + r] = heap1[r]; }
            }
            thr0 = INF; thr1 = INF;
#pragma unroll
            for (int i = 0; i < KNN; i++) { heap0[i] = INF; heap1[i] = INF; }

            MBAR_WAIT(sm + OFF_MBAR + 16, 1);
#pragma unroll
            for (int s = 0; s < 8; s++)
                ldsm4(aF[s], arow + ((((uint32_t)(2 * s + shiA)) ^ (uint32_t)(rA & 7)) << 4));
            curQ = j >> 9;
        }

        const uint32_t Bb = sm + OFF_B + buf * 32768;
        const float2* bq2 = (const float2*)(smem + OFF_BSQ + buf * 512);

        // ---- R6 tile body: two column halves, fp16 packed accumulators
#pragma unroll
        for (int half = 0; half < 2; half++) {
            uint32_t acc[8][2];
#pragma unroll
            for (int f = 0; f < 8; f++) { acc[f][0] = 0u; acc[f][1] = 0u; }

#pragma unroll
            for (int s = 0; s < 8; s++) {
                const uint32_t segoff =
                    (((uint32_t)(2 * s + shiB)) ^ (uint32_t)(rB & 7)) << 4;
#pragma unroll
                for (int jb = 0; jb < 4; jb++) {
                    uint32_t bf[4];
                    ldsm4(bf, Bb + ((half * 4 + jb) * 16 + rB) * 256 + segoff);
                    mma16816_f16(acc[2 * jb],     aF[s], bf);
                    mma16816_f16(acc[2 * jb + 1], aF[s], bf + 2);
                }
            }

#pragma unroll
            for (int f = 0; f < 8; f++) {
                float2 bq = bq2[4 * (half * 8 + f) + tig];
                float2 v0 = __half22float2(*(const __half2*)&acc[f][0]);
                float2 v1 = __half22float2(*(const __half2*)&acc[f][1]);
                top9f(fmaf(-2.0f, v0.x, bq.x), heap0, thr0);
                top9f(fmaf(-2.0f, v0.y, bq.y), heap0, thr0);
                top9f(fmaf(-2.0f, v1.x, bq.x), heap1, thr1);
                top9f(fmaf(-2.0f, v1.y, bq.y), heap1, thr1);
            }
        }

        __syncthreads();
        if (t + 2 < cnt && tid == 0) {
            const int jn = j0 + t + 2;
            MBAR_EXPECT_TX(sm + OFF_MBAR + buf * 8, 32768u + 512u);
            bulk_g2s(sm + OFF_B + buf * 32768,
                     g_bt + (size_t)(jn & 511) * TILE_HALFS, 32768u,
                     sm + OFF_MBAR + buf * 8);
            bulk_g2s(sm + OFF_BSQ + buf * 512, g_bsq + (jn & 511) * NTILE, 512u,
                     sm + OFF_MBAR + buf * 8);
        }
    }

    // ---- final flush for curQ (== lastQ)
#pragma unroll
    for (int src = 1; src < 4; src++) {
#pragma unroll
        for (int i = 0; i < KNN; i++) {
            float v0 = __shfl_sync(FULL, heap0[i], (lane & ~3) + src);
            float v1 = __shfl_sync(FULL, heap1[i], (lane & ~3) + src);
            if (tig == 0) { top9f(v0, heap0, thr0); top9f(v1, heap1, thr1); }
        }
    }
    if (tig == 0) {
        const int slot = c - ((37 * curQ) >> 2);
        const int row0 = (curQ << 7) + wid * 16 + g;
        size_t p0 = ((size_t)row0 * NSLOTS + slot) * 12;
        size_t p1 = ((size_t)(row0 + 8) * NSLOTS + slot) * 12;
#pragma unroll
        for (int r = 0; r < KNN; r++) { g_part[p0 + r] = heap0[r]; g_part[p1 + r] = heap1[r]; }
    }
}

// ---------------------------------------------------------------------------
// Finalize: per query, merge its covering-CTA lists; sqrt; mean.
// ---------------------------------------------------------------------------
__global__ void knn_finalize_kernel(float* __restrict__ out) {
    int qi = blockIdx.x * blockDim.x + threadIdx.x;
    if (qi >= M_Q) return;
    const float INF = __int_as_float(0x7f800000);
    const int Q   = qi >> 7;
    const int clo = (37 * Q) >> 2;
    const int chi = (37 * (Q + 1) - 1) >> 2;
    const int nl  = chi - clo + 1;

    float heap[KNN], thr = INF;
#pragma unroll
    for (int i = 0; i < KNN; i++) heap[i] = INF;

    const float* base = &g_part[(size_t)qi * NSLOTS * 12];
#pragma unroll 1
    for (int l = 0; l < nl; l++) {
        const float* p = base + l * 12;
#pragma unroll
        for (int r = 0; r < KNN; r++) top9f(p[r], heap, thr);
    }

    float qsq = g_qsq[qi];
    float sum = 0.0f;
#pragma unroll
    for (int i = 0; i < KNN; i++) sum += sqrtf(fmaxf(heap[i] + qsq, 0.0f));
    out[qi] = sum * (1.0f / KNN);
}

// ---------------------------------------------------------------------------
extern "C" void kernel_launch(void* const* d_in, const int* in_sizes, int n_in,
                              void* d_out, int out_size)
{
    const float* q = (const float*)d_in[0];   // features    [4096,128]
    const float* b = (const float*)d_in[1];   // memory_bank [65536,128]
    if (n_in >= 2 && in_sizes[0] > in_sizes[1]) {   // defensive ordering
        const float* tmp = q; q = b; b = tmp;
    }
    float* out = (float*)d_out;

    static uint4* p_bt = nullptr;
    static uint4* p_qt = nullptr;
    static float *p_bsq = nullptr, *p_qsq = nullptr;
    if (!p_bt) {
        cudaGetSymbolAddress((void**)&p_bt, g_bt);
        cudaGetSymbolAddress((void**)&p_qt, g_qt);
        cudaGetSymbolAddress((void**)&p_bsq, g_bsq);
        cudaGetSymbolAddress((void**)&p_qsq, g_qsq);
    }

    cudaFuncSetAttribute(knn_main_kernel,
                         cudaFuncAttributeMaxDynamicSharedMemorySize, SMEM_SZ);

    pack_norms_kernel<<<N_B * 16 / 256, 256>>>((const float4*)b, p_bt, p_bsq, N_B * 16);
    pack_norms_kernel<<<M_Q * 16 / 256, 256>>>((const float4*)q, p_qt, p_qsq, M_Q * 16);

    knn_main_kernel<<<NCTAS, THREADS, SMEM_SZ>>>();

    knn_finalize_kernel<<<M_Q / 128, 128>>>(out);
}

// round 13
// speedup vs baseline: 2.3952x; 1.0467x over previous
#include <cuda_runtime.h>
#include <cuda_fp16.h>
#include <cstdint>

#define M_Q   4096
#define N_B   65536
#define D_DIM 128
#define KNN   9
#define MTILE 128
#define NTILE 128
#define NCTAS 296                     // exactly 2 per SM on 148 SMs
#define THREADS 256
#define NSLOTS 12                     // max covering CTAs per qtile is 11
#define TILE_HALFS (128 * D_DIM)      // 16384 halves = 32KB per packed tile

// ---------------------------------------------------------------------------
// Device-global scratch
// ---------------------------------------------------------------------------
__device__ __align__(16) float g_bsq[N_B];
__device__ __align__(16) float g_qsq[M_Q];
// query-major candidate lists: [query][slot][KNN..pad12]
__device__ __align__(16) float g_part[(size_t)M_Q * NSLOTS * 12];
__device__ __align__(16) __half g_bt[(size_t)N_B * D_DIM];   // packed pre-swizzled
__device__ __align__(16) __half g_qt[(size_t)M_Q * D_DIM];

// ---------------------------------------------------------------------------
// SMEM: A 32KB, B 2x32KB, bsq 2x512B, mbarriers (buf0, buf1, A)
// ---------------------------------------------------------------------------
#define OFF_A    0
#define OFF_B    32768
#define OFF_BSQ  (32768 + 2 * 32768)        // 98304
#define OFF_MBAR (OFF_BSQ + 2 * 512)        // 99328
#define SMEM_SZ  (OFF_MBAR + 64)

// ---------------------------------------------------------------------------
// PTX helpers (sm_90-baseline)
// ---------------------------------------------------------------------------
__device__ __forceinline__ uint32_t smem_u32(const void* p) {
    uint32_t a;
    asm("{ .reg .u64 t; cvta.to.shared.u64 t, %1; cvt.u32.u64 %0, t; }" : "=r"(a) : "l"(p));
    return a;
}
__device__ __forceinline__ void ldsm4(uint32_t* r, uint32_t addr) {
    asm volatile("ldmatrix.sync.aligned.m8n8.x4.shared.b16 {%0,%1,%2,%3}, [%4];"
                 : "=r"(r[0]), "=r"(r[1]), "=r"(r[2]), "=r"(r[3]) : "r"(addr));
}
__device__ __forceinline__ void mma16816_f16(uint32_t* c, const uint32_t* a, const uint32_t* b) {
    asm volatile(
        "mma.sync.aligned.m16n8k16.row.col.f16.f16.f16.f16 "
        "{%0,%1}, {%2,%3,%4,%5}, {%6,%7}, {%0,%1};"
        : "+r"(c[0]), "+r"(c[1])
        : "r"(a[0]), "r"(a[1]), "r"(a[2]), "r"(a[3]), "r"(b[0]), "r"(b[1]));
}
#define MBAR_INIT(a, c) \
    asm volatile("mbarrier.init.shared.b64 [%0], %1;" :: "r"(a), "r"(c) : "memory")
#define MBAR_EXPECT_TX(a, tx) \
    asm volatile("mbarrier.arrive.expect_tx.shared.b64 _, [%0], %1;" :: "r"(a), "r"(tx) : "memory")
#define MBAR_WAIT(a, ph) do {                                                   \
    asm volatile(                                                               \
        "{\n\t.reg .pred P1;\n\t"                                               \
        "WAIT_LOOP_%=:\n\t"                                                     \
        "mbarrier.try_wait.parity.acquire.cta.shared::cta.b64 P1, [%0], %1, 0x989680;\n\t" \
        "@P1 bra.uni WAIT_DONE_%=;\n\t"                                         \
        "bra.uni WAIT_LOOP_%=;\n\t"                                             \
        "WAIT_DONE_%=:\n\t}"                                                    \
        :: "r"(a), "r"(ph) : "memory");                                         \
} while (0)
__device__ __forceinline__ void bulk_g2s(uint32_t dst, const void* src,
                                         uint32_t bytes, uint32_t mbar) {
    asm volatile(
        "cp.async.bulk.shared::cluster.global.mbarrier::complete_tx::bytes "
        "[%0], [%1], %2, [%3];"
        :: "r"(dst), "l"(src), "r"(bytes), "r"(mbar) : "memory");
}

// ---------------------------------------------------------------------------
// Pre-pass: fp32 -> fp16 packed pre-swizzled tiles + fused squared norms
// ---------------------------------------------------------------------------
__global__ void pack_norms_kernel(const float4* __restrict__ src,
                                  uint4* __restrict__ dst,
                                  float* __restrict__ nrm, int nchunks) {
    int i = blockIdx.x * blockDim.x + threadIdx.x;
    if (i >= nchunks) return;
    int vec = i >> 4, c = i & 15;
    int tile = vec >> 7, r = vec & 127;
    float4 a = src[2 * i];
    float4 b = src[2 * i + 1];
    __half2 h0 = __floats2half2_rn(a.x, a.y);
    __half2 h1 = __floats2half2_rn(a.z, a.w);
    __half2 h2 = __floats2half2_rn(b.x, b.y);
    __half2 h3 = __floats2half2_rn(b.z, b.w);
    uint4 o;
    o.x = *(uint32_t*)&h0; o.y = *(uint32_t*)&h1;
    o.z = *(uint32_t*)&h2; o.w = *(uint32_t*)&h3;
    uint32_t off = (uint32_t)tile * 32768 + r * 256 + (((uint32_t)(c ^ (r & 7))) << 4);
    dst[off >> 4] = o;

    float s = a.x * a.x + a.y * a.y + a.z * a.z + a.w * a.w
            + b.x * b.x + b.y * b.y + b.z * b.z + b.w * b.w;
#pragma unroll
    for (int offv = 8; offv; offv >>= 1) s += __shfl_xor_sync(0xffffffffu, s, offv);
    if (c == 0) nrm[vec] = s;
}

// ---------------------------------------------------------------------------
// Streaming top-9
// ---------------------------------------------------------------------------
__device__ __forceinline__ void top9f(float s, float (&h)[KNN], float& thr) {
    if (s < thr) {
        bool done = false;
#pragma unroll
        for (int i = 0; i < KNN; i++)
            if (!done && h[i] == thr) { h[i] = s; done = true; }
        float m = h[0];
#pragma unroll
        for (int i = 1; i < KNN; i++) m = fmaxf(m, h[i]);
        thr = m;
    }
}

// ---------------------------------------------------------------------------
// Main kernel: flattened job decomposition, segment-structured (no in-loop
// aF rewrites -> no spills). Grid = 296 CTAs; CTA c handles jobs
// [2048c/37, 2048(c+1)/37), job j = (qtile = j>>9, ntile = j&511).
// ---------------------------------------------------------------------------
__global__ void __launch_bounds__(THREADS, 2) knn_main_kernel() {
    extern __shared__ char smem[];
    const uint32_t sm = smem_u32(smem);
    const int tid  = threadIdx.x;
    const int wid  = tid >> 5;
    const int lane = tid & 31;
    const int g    = lane >> 2;
    const int tig  = lane & 3;
    const int c    = blockIdx.x;
    const int j0   = (c * 2048) / 37;
    const int j1   = ((c + 1) * 2048) / 37;
    const int cnt  = j1 - j0;                 // 55 or 56
    const int qA   = j0 >> 9;
    const int qB   = (j1 - 1) >> 9;
    const int nseg = (qA == qB) ? 1 : 2;
    const int segEnd0 = (nseg == 1) ? j1 : ((qA + 1) << 9);
    const float INF = __int_as_float(0x7f800000);
    const unsigned FULL = 0xffffffffu;

    if (tid == 0) {
        MBAR_INIT(sm + OFF_MBAR, 1);
        MBAR_INIT(sm + OFF_MBAR + 8, 1);
        MBAR_INIT(sm + OFF_MBAR + 16, 1);     // A barrier
    }
    __syncthreads();

    // ---- prologue: A(qA), B(j0), B(j0+1)
    if (tid == 0) {
        MBAR_EXPECT_TX(sm + OFF_MBAR + 16, 32768u);
        bulk_g2s(sm + OFF_A, g_qt + (size_t)qA * TILE_HALFS, 32768u, sm + OFF_MBAR + 16);
        MBAR_EXPECT_TX(sm + OFF_MBAR, 32768u + 512u);
        bulk_g2s(sm + OFF_B, g_bt + (size_t)(j0 & 511) * TILE_HALFS, 32768u, sm + OFF_MBAR);
        bulk_g2s(sm + OFF_BSQ, g_bsq + (j0 & 511) * NTILE, 512u, sm + OFF_MBAR);
        MBAR_EXPECT_TX(sm + OFF_MBAR + 8, 32768u + 512u);
        bulk_g2s(sm + OFF_B + 32768, g_bt + (size_t)((j0 + 1) & 511) * TILE_HALFS, 32768u,
                 sm + OFF_MBAR + 8);
        bulk_g2s(sm + OFF_BSQ + 512, g_bsq + ((j0 + 1) & 511) * NTILE, 512u, sm + OFF_MBAR + 8);
    }

    // lane invariants for ldmatrix addressing
    const int rA   = lane & 15;
    const int shiA = lane >> 4;
    const int rB   = (lane & 7) + ((lane >> 4) << 3);
    const int shiB = (lane >> 3) & 1;
    const uint32_t arow = sm + OFF_A + (wid * 16 + rA) * 256;

    int t = 0;   // global tile counter (drives buf + phase)

#pragma unroll 1
    for (int s = 0; s < nseg; s++) {
        const int curQ = (s == 0) ? qA : qB;
        const int jend = (s == 0) ? segEnd0 : j1;
        const int jbeg = (s == 0) ? j0 : segEnd0;

        // ---- load A fragments ONCE per segment (outside the hot loop)
        MBAR_WAIT(sm + OFF_MBAR + 16, s);
        uint32_t aF[8][4];
#pragma unroll
        for (int ss = 0; ss < 8; ss++)
            ldsm4(aF[ss], arow + ((((uint32_t)(2 * ss + shiA)) ^ (uint32_t)(rA & 7)) << 4));

        if (s == 0) {
            __syncthreads();   // all warps done reading A smem
            // prefetch second segment's A tile (aF already in regs)
            if (nseg == 2 && tid == 0) {
                MBAR_EXPECT_TX(sm + OFF_MBAR + 16, 32768u);
                bulk_g2s(sm + OFF_A, g_qt + (size_t)qB * TILE_HALFS, 32768u,
                         sm + OFF_MBAR + 16);
            }
        }

        float heap0[KNN], heap1[KNN];
        float thr0 = INF, thr1 = INF;
#pragma unroll
        for (int i = 0; i < KNN; i++) { heap0[i] = INF; heap1[i] = INF; }

        // ---- hot inner loop: exact R6 tile body
#pragma unroll 1
        for (int j = jbeg; j < jend; j++, t++) {
            const int buf = t & 1;
            MBAR_WAIT(sm + OFF_MBAR + buf * 8, (t >> 1) & 1);

            const uint32_t Bb = sm + OFF_B + buf * 32768;
            const float2* bq2 = (const float2*)(smem + OFF_BSQ + buf * 512);

#pragma unroll
            for (int half = 0; half < 2; half++) {
                uint32_t acc[8][2];
#pragma unroll
                for (int f = 0; f < 8; f++) { acc[f][0] = 0u; acc[f][1] = 0u; }

#pragma unroll
                for (int ss = 0; ss < 8; ss++) {
                    const uint32_t segoff =
                        (((uint32_t)(2 * ss + shiB)) ^ (uint32_t)(rB & 7)) << 4;
#pragma unroll
                    for (int jb = 0; jb < 4; jb++) {
                        uint32_t bf[4];
                        ldsm4(bf, Bb + ((half * 4 + jb) * 16 + rB) * 256 + segoff);
                        mma16816_f16(acc[2 * jb],     aF[ss], bf);
                        mma16816_f16(acc[2 * jb + 1], aF[ss], bf + 2);
                    }
                }

#pragma unroll
                for (int f = 0; f < 8; f++) {
                    float2 bq = bq2[4 * (half * 8 + f) + tig];
                    float2 v0 = __half22float2(*(const __half2*)&acc[f][0]);
                    float2 v1 = __half22float2(*(const __half2*)&acc[f][1]);
                    top9f(fmaf(-2.0f, v0.x, bq.x), heap0, thr0);
                    top9f(fmaf(-2.0f, v0.y, bq.y), heap0, thr0);
                    top9f(fmaf(-2.0f, v1.x, bq.x), heap1, thr1);
                    top9f(fmaf(-2.0f, v1.y, bq.y), heap1, thr1);
                }
            }

            __syncthreads();
            if (t + 2 < cnt && tid == 0) {
                const int jn = j0 + t + 2;
                MBAR_EXPECT_TX(sm + OFF_MBAR + buf * 8, 32768u + 512u);
                bulk_g2s(sm + OFF_B + buf * 32768,
                         g_bt + (size_t)(jn & 511) * TILE_HALFS, 32768u,
                         sm + OFF_MBAR + buf * 8);
                bulk_g2s(sm + OFF_BSQ + buf * 512, g_bsq + (jn & 511) * NTILE, 512u,
                         sm + OFF_MBAR + buf * 8);
            }
        }

        // ---- flush heaps for curQ: quad merge tig 1..3 -> tig 0
#pragma unroll
        for (int src = 1; src < 4; src++) {
#pragma unroll
            for (int i = 0; i < KNN; i++) {
                float v0 = __shfl_sync(FULL, heap0[i], (lane & ~3) + src);
                float v1 = __shfl_sync(FULL, heap1[i], (lane & ~3) + src);
                if (tig == 0) { top9f(v0, heap0, thr0); top9f(v1, heap1, thr1); }
            }
        }
        if (tig == 0) {
            const int slot = c - ((37 * curQ) >> 2);
            const int row0 = (curQ << 7) + wid * 16 + g;
            size_t p0 = ((size_t)row0 * NSLOTS + slot) * 12;
            size_t p1 = ((size_t)(row0 + 8) * NSLOTS + slot) * 12;
#pragma unroll
            for (int r = 0; r < KNN; r++) { g_part[p0 + r] = heap0[r]; g_part[p1 + r] = heap1[r]; }
        }
    }
}

// ---------------------------------------------------------------------------
// Finalize: per query, merge its covering-CTA lists (query-major, contiguous);
// sqrt; mean.
// ---------------------------------------------------------------------------
__global__ void knn_finalize_kernel(float* __restrict__ out) {
    int qi = blockIdx.x * blockDim.x + threadIdx.x;
    if (qi >= M_Q) return;
    const float INF = __int_as_float(0x7f800000);
    const int Q   = qi >> 7;
    const int clo = (37 * Q) >> 2;
    const int chi = (37 * (Q + 1) - 1) >> 2;
    const int nl  = chi - clo + 1;

    float heap[KNN], thr = INF;
#pragma unroll
    for (int i = 0; i < KNN; i++) heap[i] = INF;

    const float* base = &g_part[(size_t)qi * NSLOTS * 12];
#pragma unroll 1
    for (int l = 0; l < nl; l++) {
        const float* p = base + l * 12;
#pragma unroll
        for (int r = 0; r < KNN; r++) top9f(p[r], heap, thr);
    }

    float qsq = g_qsq[qi];
    float sum = 0.0f;
#pragma unroll
    for (int i = 0; i < KNN; i++) sum += sqrtf(fmaxf(heap[i] + qsq, 0.0f));
    out[qi] = sum * (1.0f / KNN);
}

// ---------------------------------------------------------------------------
extern "C" void kernel_launch(void* const* d_in, const int* in_sizes, int n_in,
                              void* d_out, int out_size)
{
    const float* q = (const float*)d_in[0];   // features    [4096,128]
    const float* b = (const float*)d_in[1];   // memory_bank [65536,128]
    if (n_in >= 2 && in_sizes[0] > in_sizes[1]) {   // defensive ordering
        const float* tmp = q; q = b; b = tmp;
    }
    float* out = (float*)d_out;

    static uint4* p_bt = nullptr;
    static uint4* p_qt = nullptr;
    static float *p_bsq = nullptr, *p_qsq = nullptr;
    if (!p_bt) {
        cudaGetSymbolAddress((void**)&p_bt, g_bt);
        cudaGetSymbolAddress((void**)&p_qt, g_qt);
        cudaGetSymbolAddress((void**)&p_bsq, g_bsq);
        cudaGetSymbolAddress((void**)&p_qsq, g_qsq);
    }

    cudaFuncSetAttribute(knn_main_kernel,
                         cudaFuncAttributeMaxDynamicSharedMemorySize, SMEM_SZ);

    pack_norms_kernel<<<N_B * 16 / 256, 256>>>((const float4*)b, p_bt, p_bsq, N_B * 16);
    pack_norms_kernel<<<M_Q * 16 / 256, 256>>>((const float4*)q, p_qt, p_qsq, M_Q * 16);

    knn_main_kernel<<<NCTAS, THREADS, SMEM_SZ>>>();

    knn_finalize_kernel<<<M_Q / 256, 256>>>(out);
}

// round 14
// speedup vs baseline: 2.6725x; 1.1158x over previous
#include <cuda_runtime.h>
#include <cuda_fp16.h>
#include <cstdint>

#define M_Q   4096
#define N_B   65536
#define D_DIM 128
#define KNN   9
#define MTILE 128
#define NTILE 128
#define NSPLIT 9                      // one-wave grid: 32*9 = 288 CTAs, 2/SM
#define NT_TOTAL (N_B / NTILE)        // 512 n-tiles
#define THREADS 256
#define PART_STRIDE 12
#define NLISTS NSPLIT
#define TILE_HALFS (128 * D_DIM)      // 16384 halves = 32KB per packed tile
#define NQTILES (M_Q / MTILE)         // 32

// ---------------------------------------------------------------------------
// Device-global scratch
// ---------------------------------------------------------------------------
__device__ __align__(16) float g_bsq[N_B];
__device__ __align__(16) float g_qsq[M_Q];
__device__ __align__(16) float g_part[NLISTS * M_Q * PART_STRIDE];
__device__ __align__(16) __half g_bt[(size_t)N_B * D_DIM];   // packed pre-swizzled
__device__ __align__(16) __half g_qt[(size_t)M_Q * D_DIM];
__device__ int g_cnt[NQTILES];        // per-qtile completion counters

// ---------------------------------------------------------------------------
// SMEM: A 32KB, B 2x32KB, bsq 2x512B, mbarriers + flag
// ---------------------------------------------------------------------------
#define OFF_A    0
#define OFF_B    32768
#define OFF_BSQ  (32768 + 2 * 32768)        // 98304
#define OFF_MBAR (OFF_BSQ + 2 * 512)        // 99328
#define SMEM_SZ  (OFF_MBAR + 64)

// ---------------------------------------------------------------------------
// PTX helpers (sm_90-baseline)
// ---------------------------------------------------------------------------
__device__ __forceinline__ uint32_t smem_u32(const void* p) {
    uint32_t a;
    asm("{ .reg .u64 t; cvta.to.shared.u64 t, %1; cvt.u32.u64 %0, t; }" : "=r"(a) : "l"(p));
    return a;
}
__device__ __forceinline__ void ldsm4(uint32_t* r, uint32_t addr) {
    asm volatile("ldmatrix.sync.aligned.m8n8.x4.shared.b16 {%0,%1,%2,%3}, [%4];"
                 : "=r"(r[0]), "=r"(r[1]), "=r"(r[2]), "=r"(r[3]) : "r"(addr));
}
__device__ __forceinline__ void mma16816_f16(uint32_t* c, const uint32_t* a, const uint32_t* b) {
    asm volatile(
        "mma.sync.aligned.m16n8k16.row.col.f16.f16.f16.f16 "
        "{%0,%1}, {%2,%3,%4,%5}, {%6,%7}, {%0,%1};"
        : "+r"(c[0]), "+r"(c[1])
        : "r"(a[0]), "r"(a[1]), "r"(a[2]), "r"(a[3]), "r"(b[0]), "r"(b[1]));
}
#define MBAR_INIT(a, c) \
    asm volatile("mbarrier.init.shared.b64 [%0], %1;" :: "r"(a), "r"(c) : "memory")
#define MBAR_EXPECT_TX(a, tx) \
    asm volatile("mbarrier.arrive.expect_tx.shared.b64 _, [%0], %1;" :: "r"(a), "r"(tx) : "memory")
#define MBAR_WAIT(a, ph) do {                                                   \
    asm volatile(                                                               \
        "{\n\t.reg .pred P1;\n\t"                                               \
        "WAIT_LOOP_%=:\n\t"                                                     \
        "mbarrier.try_wait.parity.acquire.cta.shared::cta.b64 P1, [%0], %1, 0x989680;\n\t" \
        "@P1 bra.uni WAIT_DONE_%=;\n\t"                                         \
        "bra.uni WAIT_LOOP_%=;\n\t"                                             \
        "WAIT_DONE_%=:\n\t}"                                                    \
        :: "r"(a), "r"(ph) : "memory");                                         \
} while (0)
__device__ __forceinline__ void bulk_g2s(uint32_t dst, const void* src,
                                         uint32_t bytes, uint32_t mbar) {
    asm volatile(
        "cp.async.bulk.shared::cluster.global.mbarrier::complete_tx::bytes "
        "[%0], [%1], %2, [%3];"
        :: "r"(dst), "l"(src), "r"(bytes), "r"(mbar) : "memory");
}

// ---------------------------------------------------------------------------
// Pre-pass: fp32 -> fp16 packed pre-swizzled tiles + fused squared norms.
// Also resets the per-qtile completion counters (runs before main on stream).
// ---------------------------------------------------------------------------
__global__ void pack_norms_kernel(const float4* __restrict__ src,
                                  uint4* __restrict__ dst,
                                  float* __restrict__ nrm, int nchunks) {
    if (blockIdx.x == 0 && threadIdx.x < NQTILES) g_cnt[threadIdx.x] = 0;
    int i = blockIdx.x * blockDim.x + threadIdx.x;
    if (i >= nchunks) return;
    int vec = i >> 4, c = i & 15;
    int tile = vec >> 7, r = vec & 127;
    float4 a = src[2 * i];
    float4 b = src[2 * i + 1];
    __half2 h0 = __floats2half2_rn(a.x, a.y);
    __half2 h1 = __floats2half2_rn(a.z, a.w);
    __half2 h2 = __floats2half2_rn(b.x, b.y);
    __half2 h3 = __floats2half2_rn(b.z, b.w);
    uint4 o;
    o.x = *(uint32_t*)&h0; o.y = *(uint32_t*)&h1;
    o.z = *(uint32_t*)&h2; o.w = *(uint32_t*)&h3;
    uint32_t off = (uint32_t)tile * 32768 + r * 256 + (((uint32_t)(c ^ (r & 7))) << 4);
    dst[off >> 4] = o;

    float s = a.x * a.x + a.y * a.y + a.z * a.z + a.w * a.w
            + b.x * b.x + b.y * b.y + b.z * b.z + b.w * b.w;
#pragma unroll
    for (int offv = 8; offv; offv >>= 1) s += __shfl_xor_sync(0xffffffffu, s, offv);
    if (c == 0) nrm[vec] = s;
}

// ---------------------------------------------------------------------------
// Streaming top-9
// ---------------------------------------------------------------------------
__device__ __forceinline__ void top9f(float s, float (&h)[KNN], float& thr) {
    if (s < thr) {
        bool done = false;
#pragma unroll
        for (int i = 0; i < KNN; i++)
            if (!done && h[i] == thr) { h[i] = s; done = true; }
        float m = h[0];
#pragma unroll
        for (int i = 1; i < KNN; i++) m = fmaxf(m, h[i]);
        thr = m;
    }
}

// ---------------------------------------------------------------------------
// Main kernel: exact R6 structure (grid 32x9, 2 CTAs/SM) + fused finalize.
// The 9th (last) CTA to finish a qtile merges its 81 candidates -> out.
// ---------------------------------------------------------------------------
__global__ void __launch_bounds__(THREADS, 2) knn_main_kernel(float* __restrict__ out) {
    extern __shared__ char smem[];
    const uint32_t sm = smem_u32(smem);
    const int tid  = threadIdx.x;
    const int wid  = tid >> 5;
    const int lane = tid & 31;
    const int g    = lane >> 2;
    const int tig  = lane & 3;
    const int qtile = blockIdx.x;
    const int qbase = qtile * MTILE;
    const int b0  = (NT_TOTAL * blockIdx.y) / NSPLIT;
    const int cnt = (NT_TOTAL * (blockIdx.y + 1)) / NSPLIT - b0;
    const float INF = __int_as_float(0x7f800000);
    const unsigned FULL = 0xffffffffu;

    if (tid == 0) { MBAR_INIT(sm + OFF_MBAR, 1); MBAR_INIT(sm + OFF_MBAR + 8, 1); }
    __syncthreads();

    if (tid == 0) {
        MBAR_EXPECT_TX(sm + OFF_MBAR, 32768u + 32768u + 512u);
        bulk_g2s(sm + OFF_A, g_qt + (size_t)qtile * TILE_HALFS, 32768u, sm + OFF_MBAR);
        bulk_g2s(sm + OFF_B, g_bt + (size_t)b0 * TILE_HALFS, 32768u, sm + OFF_MBAR);
        bulk_g2s(sm + OFF_BSQ, g_bsq + b0 * NTILE, 512u, sm + OFF_MBAR);
        MBAR_EXPECT_TX(sm + OFF_MBAR + 8, 32768u + 512u);
        bulk_g2s(sm + OFF_B + 32768, g_bt + (size_t)(b0 + 1) * TILE_HALFS, 32768u,
                 sm + OFF_MBAR + 8);
        bulk_g2s(sm + OFF_BSQ + 512, g_bsq + (b0 + 1) * NTILE, 512u, sm + OFF_MBAR + 8);
    }

    MBAR_WAIT(sm + OFF_MBAR, 0);

    // preload A fragments (reused for all tiles)
    const int rA   = lane & 15;
    const int shiA = lane >> 4;
    const uint32_t arow = sm + OFF_A + (wid * 16 + rA) * 256;
    uint32_t aF[8][4];
#pragma unroll
    for (int s = 0; s < 8; s++)
        ldsm4(aF[s], arow + ((((uint32_t)(2 * s + shiA)) ^ (uint32_t)(rA & 7)) << 4));

    float heap0[KNN], heap1[KNN];
    float thr0 = INF, thr1 = INF;
#pragma unroll
    for (int i = 0; i < KNN; i++) { heap0[i] = INF; heap1[i] = INF; }

    const int rB   = (lane & 7) + ((lane >> 4) << 3);
    const int shiB = (lane >> 3) & 1;

#pragma unroll 1
    for (int t = 0; t < cnt; t++) {
        const int buf = t & 1;

        if (t > 0) MBAR_WAIT(sm + OFF_MBAR + buf * 8, (t >> 1) & 1);

        const uint32_t Bb = sm + OFF_B + buf * 32768;
        const float2* bq2 = (const float2*)(smem + OFF_BSQ + buf * 512);

#pragma unroll
        for (int half = 0; half < 2; half++) {
            uint32_t acc[8][2];
#pragma unroll
            for (int f = 0; f < 8; f++) { acc[f][0] = 0u; acc[f][1] = 0u; }

#pragma unroll
            for (int s = 0; s < 8; s++) {
                const uint32_t segoff =
                    (((uint32_t)(2 * s + shiB)) ^ (uint32_t)(rB & 7)) << 4;
#pragma unroll
                for (int jb = 0; jb < 4; jb++) {
                    uint32_t bf[4];
                    ldsm4(bf, Bb + ((half * 4 + jb) * 16 + rB) * 256 + segoff);
                    mma16816_f16(acc[2 * jb],     aF[s], bf);
                    mma16816_f16(acc[2 * jb + 1], aF[s], bf + 2);
                }
            }

#pragma unroll
            for (int f = 0; f < 8; f++) {
                float2 bq = bq2[4 * (half * 8 + f) + tig];
                float2 v0 = __half22float2(*(const __half2*)&acc[f][0]);
                float2 v1 = __half22float2(*(const __half2*)&acc[f][1]);
                top9f(fmaf(-2.0f, v0.x, bq.x), heap0, thr0);
                top9f(fmaf(-2.0f, v0.y, bq.y), heap0, thr0);
                top9f(fmaf(-2.0f, v1.x, bq.x), heap1, thr1);
                top9f(fmaf(-2.0f, v1.y, bq.y), heap1, thr1);
            }
        }

        __syncthreads();
        if (t + 2 < cnt && tid == 0) {
            MBAR_EXPECT_TX(sm + OFF_MBAR + buf * 8, 32768u + 512u);
            bulk_g2s(sm + OFF_B + buf * 32768,
                     g_bt + (size_t)(b0 + t + 2) * TILE_HALFS, 32768u,
                     sm + OFF_MBAR + buf * 8);
            bulk_g2s(sm + OFF_BSQ + buf * 512, g_bsq + (b0 + t + 2) * NTILE, 512u,
                     sm + OFF_MBAR + buf * 8);
        }
    }

    // ---- quad merge: lanes tig=1..3 ship their heaps to tig=0
#pragma unroll
    for (int src = 1; src < 4; src++) {
#pragma unroll
        for (int i = 0; i < KNN; i++) {
            float v0 = __shfl_sync(FULL, heap0[i], (lane & ~3) + src);
            float v1 = __shfl_sync(FULL, heap1[i], (lane & ~3) + src);
            if (tig == 0) { top9f(v0, heap0, thr0); top9f(v1, heap1, thr1); }
        }
    }

    if (tig == 0) {
        const int row0 = qbase + wid * 16 + g;
        size_t p0 = ((size_t)blockIdx.y * M_Q + row0) * PART_STRIDE;
        size_t p1 = ((size_t)blockIdx.y * M_Q + row0 + 8) * PART_STRIDE;
#pragma unroll
        for (int r = 0; r < KNN; r++) {
            g_part[p0 + r] = heap0[r];
            g_part[p1 + r] = heap1[r];
        }
    }

    // ---- fused finalize: last CTA of this qtile merges and writes out
    __threadfence();
    __syncthreads();
    int* flag = (int*)(smem + OFF_MBAR + 32);
    if (tid == 0) *flag = atomicAdd(&g_cnt[qtile], 1);
    __syncthreads();
    if (*flag == NSPLIT - 1) {
        if (tid < MTILE) {
            const int qi = qbase + tid;
            float heap[KNN], thr = INF;
#pragma unroll
            for (int i = 0; i < KNN; i++) heap[i] = INF;
#pragma unroll 1
            for (int l = 0; l < NLISTS; l++) {
                const float* p = &g_part[((size_t)l * M_Q + qi) * PART_STRIDE];
#pragma unroll
                for (int r = 0; r < KNN; r++) top9f(p[r], heap, thr);
            }
            float qsq = g_qsq[qi];
            float sum = 0.0f;
#pragma unroll
            for (int i = 0; i < KNN; i++) sum += sqrtf(fmaxf(heap[i] + qsq, 0.0f));
            out[qi] = sum * (1.0f / KNN);
        }
    }
}

// ---------------------------------------------------------------------------
extern "C" void kernel_launch(void* const* d_in, const int* in_sizes, int n_in,
                              void* d_out, int out_size)
{
    const float* q = (const float*)d_in[0];   // features    [4096,128]
    const float* b = (const float*)d_in[1];   // memory_bank [65536,128]
    if (n_in >= 2 && in_sizes[0] > in_sizes[1]) {   // defensive ordering
        const float* tmp = q; q = b; b = tmp;
    }
    float* out = (float*)d_out;

    static uint4* p_bt = nullptr;
    static uint4* p_qt = nullptr;
    static float *p_bsq = nullptr, *p_qsq = nullptr;
    if (!p_bt) {
        cudaGetSymbolAddress((void**)&p_bt, g_bt);
        cudaGetSymbolAddress((void**)&p_qt, g_qt);
        cudaGetSymbolAddress((void**)&p_bsq, g_bsq);
        cudaGetSymbolAddress((void**)&p_qsq, g_qsq);
    }

    cudaFuncSetAttribute(knn_main_kernel,
                         cudaFuncAttributeMaxDynamicSharedMemorySize, SMEM_SZ);

    pack_norms_kernel<<<N_B * 16 / 256, 256>>>((const float4*)b, p_bt, p_bsq, N_B * 16);
    pack_norms_kernel<<<M_Q * 16 / 256, 256>>>((const float4*)q, p_qt, p_qsq, M_Q * 16);

    dim3 grid(M_Q / MTILE, NSPLIT);
    knn_main_kernel<<<grid, THREADS, SMEM_SZ>>>(out);
}